// round 13
// baseline (speedup 1.0000x reference)
#include <cuda_runtime.h>
#include <cuda_fp16.h>

#define NN 100000
#define EE 1250000
#define HH 64
#define TOT (EE + NN)

#define FMA2(d, a, b) asm("fma.rn.f32x2 %0, %1, %2, %0;" : "+l"(d) : "l"(a), "l"(b))

// ---------------- scratch (__device__ globals; no runtime allocation) ----------------
__device__ __align__(16) float  d_wsum[NN];        // weighted degree (float atomics)
__device__ __align__(16) float  d_dinv[NN];        // rsqrt of weighted degree
__device__ __align__(16) int    d_cnt[NN + 1];     // in-degree counts (incl. self loop)
__device__ __align__(16) int    d_part[NN + 1];    // per-block scan partials
__device__ __align__(16) int    d_bsums[128];      // block sums for scan
__device__ __align__(16) int    d_off[NN + 1];     // CSR row offsets
__device__ __align__(16) int    d_pos[NN];         // fill cursors
__device__ __align__(16) int2   d_csr_pair[TOT];   // {src, normalized-weight bits}
__device__ __align__(16) __half d_hA16[NN * HH];   // fp16 feature ping
__device__ __align__(16) __half d_hB16[NN * HH];   // fp16 feature pong

// ---------------- graph preprocessing ----------------
__global__ void k_init() {
    int i = blockIdx.x * blockDim.x + threadIdx.x;
    if (i < NN) { d_cnt[i] = 1; d_wsum[i] = 1.0f; }   // self loop
    if (i == 0) d_cnt[NN] = 0;
}

__global__ void k_deg(const int* __restrict__ ei, const float* __restrict__ ea) {
    int e = blockIdx.x * blockDim.x + threadIdx.x;
    if (e < EE) {
        int dd = ei[EE + e];                 // row 1 = dst
        atomicAdd(&d_cnt[dd], 1);
        atomicAdd(&d_wsum[dd], ea[e]);
    }
}

// stage 1 of exclusive scan of d_cnt[0..NN]
__global__ void k_scan1() {
    __shared__ int sm[1024];
    int gid = blockIdx.x * 1024 + threadIdx.x;
    int v = (gid <= NN) ? d_cnt[gid] : 0;
    sm[threadIdx.x] = v;
    __syncthreads();
    for (int off = 1; off < 1024; off <<= 1) {
        int t = (threadIdx.x >= off) ? sm[threadIdx.x - off] : 0;
        __syncthreads();
        sm[threadIdx.x] += t;
        __syncthreads();
    }
    if (gid <= NN) d_part[gid] = sm[threadIdx.x] - v;   // exclusive within block
    if (threadIdx.x == 1023) d_bsums[blockIdx.x] = sm[1023];
}

// fused: block-sum scan (redundant per block) + final offsets + dinv = rsqrt(wsum)
__global__ void k_scan3f(int nb) {     // 256 threads
    __shared__ int bs[128];
    int t = threadIdx.x;
    if (t < 128) bs[t] = (t < nb) ? d_bsums[t] : 0;
    __syncthreads();
    for (int off = 1; off < 128; off <<= 1) {
        int u = (t >= off && t < 128) ? bs[t - off] : 0;
        __syncthreads();
        if (t < 128) bs[t] += u;       // inclusive
        __syncthreads();
    }
    int gid = blockIdx.x * 256 + t;
    if (gid <= NN) {
        int blk = gid >> 10;
        int o = d_part[gid] + (blk ? bs[blk - 1] : 0);
        d_off[gid] = o;
        if (gid < NN) {
            d_pos[gid]  = o;
            d_dinv[gid] = rsqrtf(d_wsum[gid]);
        }
    }
}

// fill CSR with NORMALIZED weights directly (dinv ready)
__global__ void k_fill(const int* __restrict__ ei, const float* __restrict__ ea) {
    int idx = blockIdx.x * blockDim.x + threadIdx.x;
    if (idx < EE) {
        int s  = ei[idx];                    // row 0 = src
        int dd = ei[EE + idx];               // row 1 = dst
        float w = d_dinv[s] * ea[idx] * d_dinv[dd];
        int p = atomicAdd(&d_pos[dd], 1);
        d_csr_pair[p] = make_int2(s, __float_as_int(w));
    } else if (idx < TOT) {
        int i = idx - EE;
        float di = d_dinv[i];
        int p = atomicAdd(&d_pos[i], 1);
        d_csr_pair[p] = make_int2(i, __float_as_int(di * di));
    }
}

// ---------------- layer 1: scalar aggregate (x is N x 1), rank-1 expand, fp16 out ----------------
__global__ void k_layer1(const float* __restrict__ x, const float* __restrict__ W1,
                         const float* __restrict__ b1) {
    int i = blockIdx.x * blockDim.x + threadIdx.x;
    if (i >= NN) return;
    int beg = d_off[i], end = d_off[i + 1];
    float s = 0.f;
    for (int p = beg; p < end; p++) {
        int2 pr = d_csr_pair[p];
        s = fmaf(__int_as_float(pr.y), x[pr.x], s);
    }
    const float4* W4 = (const float4*)W1;
    const float4* B4 = (const float4*)b1;
    __align__(16) __half2 hbuf[32];
#pragma unroll
    for (int j = 0; j < 16; j++) {
        float4 w = W4[j], b = B4[j];
        float rx = fmaxf(fmaf(s, w.x, b.x), 0.f);
        float ry = fmaxf(fmaf(s, w.y, b.y), 0.f);
        float rz = fmaxf(fmaf(s, w.z, b.z), 0.f);
        float rw = fmaxf(fmaf(s, w.w, b.w), 0.f);
        hbuf[2 * j]     = __floats2half2_rn(rx, ry);
        hbuf[2 * j + 1] = __floats2half2_rn(rz, rw);
    }
    uint4* dst = (uint4*)(d_hA16 + i * HH);
    const uint4* srcp = (const uint4*)hbuf;
#pragma unroll
    for (int k = 0; k < 8; k++) dst[k] = srcp[k];
}

// ---------------- fused layer: hout = relu( Agg(hin) @ W + b ), fp16 in/out ----------------
// Phase 1: warp gathers (2 nodes/warp, 16 lanes/node, 8B/lane) -> smem fp32 tile As[64][68]
// Phase 2: block GEMM 64x64x64 from As x Ws (FMA2), bias+relu, fp16 store
__global__ void __launch_bounds__(256) k_layer(int sel, const float* __restrict__ W,
                                               const float* __restrict__ bias) {
    __shared__ float  As[64 * 68];
    __shared__ float4 Ws[64 * 16];
    const __half* hin = sel ? d_hB16 : d_hA16;
    __half*      hout = sel ? d_hA16 : d_hB16;
    int tid  = threadIdx.x;
    int base = blockIdx.x * 64;

    // stage W (overlaps phase 1; consumed only after the sync)
    const float4* W4 = (const float4*)W;
    for (int i = tid; i < 1024; i += 256) Ws[i] = W4[i];

    // ---- phase 1: aggregate ----
    const unsigned long long* __restrict__ g = (const unsigned long long*)hin; // [NN][16]
    int lane = tid & 31, wid = tid >> 5;
    int hl = lane & 15, half = lane >> 4;
#pragma unroll
    for (int p = 0; p < 4; p++) {
        int ln = wid * 8 + p * 2 + half;       // local node 0..63
        int node = base + ln;
        float a0 = 0.f, a1 = 0.f, a2 = 0.f, a3 = 0.f;
        if (node < NN) {
            int beg = d_off[node], end = d_off[node + 1];
#pragma unroll 2
            for (int t = beg; t < end; t++) {
                int2 pr = d_csr_pair[t];                    // broadcast within half-warp
                float w = __int_as_float(pr.y);
                unsigned long long hv = g[pr.x * 16 + hl];  // coalesced 128B row
                unsigned int lo = (unsigned int)hv, hi = (unsigned int)(hv >> 32);
                float2 f0 = __half22float2(*reinterpret_cast<__half2*>(&lo));
                float2 f1 = __half22float2(*reinterpret_cast<__half2*>(&hi));
                a0 = fmaf(w, f0.x, a0);
                a1 = fmaf(w, f0.y, a1);
                a2 = fmaf(w, f1.x, a2);
                a3 = fmaf(w, f1.y, a3);
            }
        }
        *(float4*)&As[ln * 68 + 4 * hl] = make_float4(a0, a1, a2, a3);
    }
    __syncthreads();

    // ---- phase 2: GEMM + epilogue ----
    int r = tid >> 2, q = tid & 3;             // node row r, output quarter q
    unsigned long long acc[8];
#pragma unroll
    for (int j = 0; j < 8; j++) acc[j] = 0ull;

#pragma unroll 4
    for (int k = 0; k < 64; k++) {
        float a = As[r * 68 + k];
        unsigned long long aa;
        asm("mov.b64 %0, {%1, %1};" : "=l"(aa) : "f"(a));
        const ulonglong2* wp = (const ulonglong2*)(Ws + k * 16 + q * 4);
#pragma unroll
        for (int i = 0; i < 4; i++) {
            ulonglong2 w2 = wp[i];
            FMA2(acc[2 * i],     aa, w2.x);
            FMA2(acc[2 * i + 1], aa, w2.y);
        }
    }

    int node = base + r;
    if (node < NN) {
        const float2* B2 = (const float2*)(bias + 16 * q);
        __align__(16) __half2 hb[8];
#pragma unroll
        for (int i = 0; i < 8; i++) {
            float lo, hi;
            asm("mov.b64 {%0, %1}, %2;" : "=f"(lo), "=f"(hi) : "l"(acc[i]));
            float2 b = B2[i];
            hb[i] = __floats2half2_rn(fmaxf(lo + b.x, 0.f), fmaxf(hi + b.y, 0.f));
        }
        uint4* dst = (uint4*)(hout + node * HH + 16 * q);
        dst[0] = ((const uint4*)hb)[0];
        dst[1] = ((const uint4*)hb)[1];
    }
}

// ---------------- fused final MLP: out = relu(h5 @ fW1 + fb1) @ fW2 + fb2 ----------------
__global__ void __launch_bounds__(256) k_final(const float* __restrict__ fW1,
                                               const float* __restrict__ fb1,
                                               const float* __restrict__ fW2,
                                               const float* __restrict__ fb2,
                                               float* __restrict__ out) {
    __shared__ float  As[64 * 68];
    __shared__ float4 Ws[64 * 16];
    const unsigned long long* __restrict__ g = (const unsigned long long*)d_hA16; // h5
    int tid  = threadIdx.x;
    int base = blockIdx.x * 64;

    const float4* W4 = (const float4*)fW1;
    for (int i = tid; i < 1024; i += 256) Ws[i] = W4[i];

    // stage h5 (fp16 -> fp32 smem)
    for (int i = tid; i < 1024; i += 256) {
        int ln = i >> 4, c = i & 15;
        unsigned long long hv = (base + ln < NN) ? g[(base + ln) * 16 + c] : 0ull;
        unsigned int lo = (unsigned int)hv, hi = (unsigned int)(hv >> 32);
        float2 f0 = __half22float2(*reinterpret_cast<__half2*>(&lo));
        float2 f1 = __half22float2(*reinterpret_cast<__half2*>(&hi));
        *(float4*)&As[ln * 68 + 4 * c] = make_float4(f0.x, f0.y, f1.x, f1.y);
    }
    __syncthreads();

    int r = tid >> 2, q = tid & 3;
    unsigned long long acc[8];
#pragma unroll
    for (int j = 0; j < 8; j++) acc[j] = 0ull;

#pragma unroll 4
    for (int k = 0; k < 64; k++) {
        float a = As[r * 68 + k];
        unsigned long long aa;
        asm("mov.b64 %0, {%1, %1};" : "=l"(aa) : "f"(a));
        const ulonglong2* wp = (const ulonglong2*)(Ws + k * 16 + q * 4);
#pragma unroll
        for (int i = 0; i < 4; i++) {
            ulonglong2 w2 = wp[i];
            FMA2(acc[2 * i],     aa, w2.x);
            FMA2(acc[2 * i + 1], aa, w2.y);
        }
    }

    // head: z = relu(acc + fb1); partial dot with fW2; reduce over the 4 quarter-threads
    const float2* B2 = (const float2*)(fb1 + 16 * q);
    const float2* V2 = (const float2*)(fW2 + 16 * q);
    float part = 0.f;
#pragma unroll
    for (int i = 0; i < 8; i++) {
        float lo, hi;
        asm("mov.b64 {%0, %1}, %2;" : "=f"(lo), "=f"(hi) : "l"(acc[i]));
        float2 b = B2[i], v = V2[i];
        part = fmaf(fmaxf(lo + b.x, 0.f), v.x, part);
        part = fmaf(fmaxf(hi + b.y, 0.f), v.y, part);
    }
    part += __shfl_xor_sync(0xffffffffu, part, 1);
    part += __shfl_xor_sync(0xffffffffu, part, 2);
    int node = base + r;
    if (q == 0 && node < NN) out[node] = part + fb2[0];
}

// ---------------- launch ----------------
extern "C" void kernel_launch(void* const* d_in, const int* in_sizes, int n_in,
                              void* d_out, int out_size) {
    const float* x   = (const float*)d_in[0];
    const int*   ei  = (const int*)d_in[1];    // int32 (JAX default x64-disabled)
    const float* ea  = (const float*)d_in[2];
    const float* W1  = (const float*)d_in[3];
    const float* b1  = (const float*)d_in[4];
    const float* W2  = (const float*)d_in[5];
    const float* b2  = (const float*)d_in[6];
    const float* W3  = (const float*)d_in[7];
    const float* b3  = (const float*)d_in[8];
    const float* W4  = (const float*)d_in[9];
    const float* b4  = (const float*)d_in[10];
    const float* W5  = (const float*)d_in[11];
    const float* b5  = (const float*)d_in[12];
    const float* fW1 = (const float*)d_in[13];
    const float* fb1 = (const float*)d_in[14];
    const float* fW2 = (const float*)d_in[15];
    const float* fb2 = (const float*)d_in[16];
    float* out = (float*)d_out;

    const int TB = 256;
    int nblkN  = (NN + TB - 1) / TB;
    int nblkE  = (EE + TB - 1) / TB;
    int nblkT  = (TOT + TB - 1) / TB;
    int nblkN1 = (NN + 1 + TB - 1) / TB;
    int scanB  = (NN + 1 + 1023) / 1024;          // 98
    int layerB = (NN + 63) / 64;                  // 1563

    // graph prep
    k_init  <<<nblkN, TB>>>();
    k_deg   <<<nblkE, TB>>>(ei, ea);
    k_scan1 <<<scanB, 1024>>>();
    k_scan3f<<<nblkN1, TB>>>(scanB);
    k_fill  <<<nblkT, TB>>>(ei, ea);

    // layer 1 (rank-1): h1 -> hA16
    k_layer1<<<nblkN, TB>>>(x, W1, b1);

    // fused GCN layers (aggregate-first): A->B->A->B->A
    k_layer<<<layerB, TB>>>(0, W2, b2);
    k_layer<<<layerB, TB>>>(1, W3, b3);
    k_layer<<<layerB, TB>>>(0, W4, b4);
    k_layer<<<layerB, TB>>>(1, W5, b5);

    // fused head (reads hA16 = h5)
    k_final<<<layerB, TB>>>(fW1, fb1, fW2, fb2, out);
}

// round 14
// speedup vs baseline: 1.5656x; 1.5656x over previous
#include <cuda_runtime.h>
#include <cuda_fp16.h>

#define NN 100000
#define EE 1250000
#define HH 64
#define TOT (EE + NN)

#define FMA2(d, a, b) asm("fma.rn.f32x2 %0, %1, %2, %0;" : "+l"(d) : "l"(a), "l"(b))

// ---------------- scratch (__device__ globals; no runtime allocation) ----------------
__device__ __align__(16) float  d_wsum[NN];        // weighted degree (float atomics)
__device__ __align__(16) float  d_dinv[NN];        // rsqrt of weighted degree
__device__ __align__(16) int    d_cnt[NN + 1];     // in-degree counts (incl. self loop)
__device__ __align__(16) int    d_part[NN + 1];    // per-block scan partials
__device__ __align__(16) int    d_bsums[128];      // block sums for scan
__device__ __align__(16) int    d_off[NN + 1];     // CSR row offsets
__device__ __align__(16) int    d_pos[NN];         // fill cursors
__device__ __align__(16) int2   d_csr_pair[TOT];   // {src, normalized-weight bits}
__device__ __align__(16) float  d_hA[NN * HH];
__device__ __align__(16) float  d_hB[NN * HH];
__device__ __align__(16) __half d_g16[NN * HH];    // fp16-staged GEMM output (gathered)

// ---------------- graph preprocessing ----------------
__global__ void k_init() {
    int i = blockIdx.x * blockDim.x + threadIdx.x;
    if (i < NN) { d_cnt[i] = 1; d_wsum[i] = 1.0f; }   // self loop
    if (i == 0) d_cnt[NN] = 0;
}

__global__ void k_deg(const int* __restrict__ ei, const float* __restrict__ ea) {
    int e = blockIdx.x * blockDim.x + threadIdx.x;
    if (e < EE) {
        int dd = ei[EE + e];                 // row 1 = dst
        atomicAdd(&d_cnt[dd], 1);
        atomicAdd(&d_wsum[dd], ea[e]);
    }
}

// stage 1 of exclusive scan of d_cnt[0..NN]
__global__ void k_scan1() {
    __shared__ int sm[1024];
    int gid = blockIdx.x * 1024 + threadIdx.x;
    int v = (gid <= NN) ? d_cnt[gid] : 0;
    sm[threadIdx.x] = v;
    __syncthreads();
    for (int off = 1; off < 1024; off <<= 1) {
        int t = (threadIdx.x >= off) ? sm[threadIdx.x - off] : 0;
        __syncthreads();
        sm[threadIdx.x] += t;
        __syncthreads();
    }
    if (gid <= NN) d_part[gid] = sm[threadIdx.x] - v;   // exclusive within block
    if (threadIdx.x == 1023) d_bsums[blockIdx.x] = sm[1023];
}

// fused: block-sum scan (redundant per block) + final offsets + dinv = rsqrt(wsum)
__global__ void k_scan3f(int nb) {     // 256 threads
    __shared__ int bs[128];
    int t = threadIdx.x;
    if (t < 128) bs[t] = (t < nb) ? d_bsums[t] : 0;
    __syncthreads();
    for (int off = 1; off < 128; off <<= 1) {
        int u = (t >= off && t < 128) ? bs[t - off] : 0;
        __syncthreads();
        if (t < 128) bs[t] += u;       // inclusive
        __syncthreads();
    }
    int gid = blockIdx.x * 256 + t;
    if (gid <= NN) {
        int blk = gid >> 10;
        int o = d_part[gid] + (blk ? bs[blk - 1] : 0);
        d_off[gid] = o;
        if (gid < NN) {
            d_pos[gid]  = o;
            d_dinv[gid] = rsqrtf(d_wsum[gid]);
        }
    }
}

// fill CSR with NORMALIZED weights directly (dinv ready)
__global__ void k_fill(const int* __restrict__ ei, const float* __restrict__ ea) {
    int idx = blockIdx.x * blockDim.x + threadIdx.x;
    if (idx < EE) {
        int s  = ei[idx];                    // row 0 = src
        int dd = ei[EE + idx];               // row 1 = dst
        float w = d_dinv[s] * ea[idx] * d_dinv[dd];
        int p = atomicAdd(&d_pos[dd], 1);
        d_csr_pair[p] = make_int2(s, __float_as_int(w));
    } else if (idx < TOT) {
        int i = idx - EE;
        float di = d_dinv[i];
        int p = atomicAdd(&d_pos[i], 1);
        d_csr_pair[p] = make_int2(i, __float_as_int(di * di));
    }
}

// ---------------- layer 1: scalar aggregate (x is N x 1), rank-1 expand, fp32 out ----------------
__global__ void k_layer1(const float* __restrict__ x, const float* __restrict__ W1,
                         const float* __restrict__ b1) {
    int i = blockIdx.x * blockDim.x + threadIdx.x;
    if (i >= NN) return;
    int beg = d_off[i], end = d_off[i + 1];
    float s = 0.f;
    for (int p = beg; p < end; p++) {
        int2 pr = d_csr_pair[p];
        s = fmaf(__int_as_float(pr.y), x[pr.x], s);
    }
    const float4* W4 = (const float4*)W1;
    const float4* B4 = (const float4*)b1;
    float4* o = (float4*)(d_hA + i * HH);
#pragma unroll
    for (int j = 0; j < 16; j++) {
        float4 w = W4[j], b = B4[j], r;
        r.x = fmaxf(fmaf(s, w.x, b.x), 0.f);
        r.y = fmaxf(fmaf(s, w.y, b.y), 0.f);
        r.z = fmaxf(fmaf(s, w.z, b.z), 0.f);
        r.w = fmaxf(fmaf(s, w.w, b.w), 0.f);
        o[j] = r;
    }
}

// ---------------- GEMM: g16 = half(A @ W) via packed f32x2 FMA ----------------
__global__ void __launch_bounds__(64) k_gemm(int asel, const float* __restrict__ W) {
    __shared__ float  As[64 * 65];
    __shared__ float4 Ws[64 * 16];
    const float* A = asel ? d_hB : d_hA;
    int tid  = threadIdx.x;
    int base = blockIdx.x * 64;

    const float4* W4 = (const float4*)W;
    for (int i = tid; i < 64 * 16; i += 64) Ws[i] = W4[i];
    for (int i = tid; i < 64 * 64; i += 64) {
        int r = i >> 6, c = i & 63;
        int node = base + r;
        As[r * 65 + c] = (node < NN) ? A[node * HH + c] : 0.f;
    }
    __syncthreads();

    unsigned long long acc[32];
#pragma unroll
    for (int j = 0; j < 32; j++) acc[j] = 0ull;   // bit pattern {0.f, 0.f}

#pragma unroll 4
    for (int k = 0; k < 64; k++) {
        float a = As[tid * 65 + k];
        unsigned long long aa;
        asm("mov.b64 %0, {%1, %1};" : "=l"(aa) : "f"(a));
        const ulonglong2* wrow = (const ulonglong2*)&Ws[k * 16];
#pragma unroll
        for (int j = 0; j < 16; j++) {
            ulonglong2 w2 = wrow[j];
            FMA2(acc[2 * j],     aa, w2.x);
            FMA2(acc[2 * j + 1], aa, w2.y);
        }
    }

    int node = base + tid;
    if (node < NN) {
        __align__(16) __half2 hbuf[32];
#pragma unroll
        for (int j = 0; j < 32; j++) {
            float lo, hi;
            asm("mov.b64 {%0, %1}, %2;" : "=f"(lo), "=f"(hi) : "l"(acc[j]));
            hbuf[j] = __floats2half2_rn(lo, hi);
        }
        uint4* dst = (uint4*)(d_g16 + node * HH);
        const uint4* srcp = (const uint4*)hbuf;
#pragma unroll
        for (int i = 0; i < 8; i++) dst[i] = srcp[i];
    }
}

// ---------------- aggregate: 4 nodes per warp, 8 lanes per node, LDG.128 gathers ----------------
// out[node] = relu( sum_j w_ij * g16[j] + b );  lane ql covers features [8ql, 8ql+8)
__global__ void __launch_bounds__(256) k_agg(int osel, const float* __restrict__ bias) {
    float* out = osel ? d_hB : d_hA;
    const uint4* __restrict__ g = (const uint4*)d_g16;   // [NN][8] x 16B (128B rows)
    int gwarp = (blockIdx.x * blockDim.x + threadIdx.x) >> 5;
    int lane  = threadIdx.x & 31;
    int ql = lane & 7, grp = lane >> 3;
    unsigned gm = 0xffu << (grp * 8);            // segment mask (8 lanes)
    int node = gwarp * 4 + grp;                  // NN % 4 == 0; grid sized exactly

    int beg = d_off[node], end = d_off[node + 1];
    int n = end - beg;
    int nmax = n;
    nmax = max(nmax, __shfl_xor_sync(0xffffffffu, nmax, 8));
    nmax = max(nmax, __shfl_xor_sync(0xffffffffu, nmax, 16));

    float a0 = 0.f, a1 = 0.f, a2 = 0.f, a3 = 0.f, a4 = 0.f, a5 = 0.f, a6 = 0.f, a7 = 0.f;
    for (int cb = 0; cb < nmax; cb += 8) {
        int jj = 0; float ww = 0.f;
        int my = cb + ql;
        if (my < n) {                            // 64B coalesced pair chunk per group
            int2 p = d_csr_pair[beg + my];
            jj = p.x; ww = __int_as_float(p.y);
        }
        int rem = n - cb;                        // group-uniform
        if (rem >= 8) {                          // fast path: 8 independent LDG.128
#pragma unroll
            for (int t = 0; t < 8; t++) {
                int   j2 = __shfl_sync(gm, jj, t, 8);
                float w2 = __shfl_sync(gm, ww, t, 8);
                uint4 hv = g[j2 * 8 + ql];
                float2 f0 = __half22float2(*reinterpret_cast<__half2*>(&hv.x));
                float2 f1 = __half22float2(*reinterpret_cast<__half2*>(&hv.y));
                float2 f2 = __half22float2(*reinterpret_cast<__half2*>(&hv.z));
                float2 f3 = __half22float2(*reinterpret_cast<__half2*>(&hv.w));
                a0 = fmaf(w2, f0.x, a0); a1 = fmaf(w2, f0.y, a1);
                a2 = fmaf(w2, f1.x, a2); a3 = fmaf(w2, f1.y, a3);
                a4 = fmaf(w2, f2.x, a4); a5 = fmaf(w2, f2.y, a5);
                a6 = fmaf(w2, f3.x, a6); a7 = fmaf(w2, f3.y, a7);
            }
        } else {                                 // ragged tail (group-uniform count)
            for (int t = 0; t < rem; t++) {
                int   j2 = __shfl_sync(gm, jj, t, 8);
                float w2 = __shfl_sync(gm, ww, t, 8);
                uint4 hv = g[j2 * 8 + ql];
                float2 f0 = __half22float2(*reinterpret_cast<__half2*>(&hv.x));
                float2 f1 = __half22float2(*reinterpret_cast<__half2*>(&hv.y));
                float2 f2 = __half22float2(*reinterpret_cast<__half2*>(&hv.z));
                float2 f3 = __half22float2(*reinterpret_cast<__half2*>(&hv.w));
                a0 = fmaf(w2, f0.x, a0); a1 = fmaf(w2, f0.y, a1);
                a2 = fmaf(w2, f1.x, a2); a3 = fmaf(w2, f1.y, a3);
                a4 = fmaf(w2, f2.x, a4); a5 = fmaf(w2, f2.y, a5);
                a6 = fmaf(w2, f3.x, a6); a7 = fmaf(w2, f3.y, a7);
            }
        }
    }

    const float4* B4 = (const float4*)(bias + 8 * ql);
    float4 b0 = B4[0], b1 = B4[1];
    float4 r0, r1;
    r0.x = fmaxf(a0 + b0.x, 0.f); r0.y = fmaxf(a1 + b0.y, 0.f);
    r0.z = fmaxf(a2 + b0.z, 0.f); r0.w = fmaxf(a3 + b0.w, 0.f);
    r1.x = fmaxf(a4 + b1.x, 0.f); r1.y = fmaxf(a5 + b1.y, 0.f);
    r1.z = fmaxf(a6 + b1.z, 0.f); r1.w = fmaxf(a7 + b1.w, 0.f);
    float4* o = (float4*)(out + node * HH + 8 * ql);
    o[0] = r0; o[1] = r1;
}

// ---------------- fused final MLP: out = relu(h5 @ fW1 + fb1) @ fW2 + fb2 ----------------
__global__ void __launch_bounds__(64) k_final(const float* __restrict__ fW1,
                                              const float* __restrict__ fb1,
                                              const float* __restrict__ fW2,
                                              const float* __restrict__ fb2,
                                              float* __restrict__ out) {
    __shared__ float  As[64 * 65];
    __shared__ float4 Ws[64 * 16];
    const float* A = d_hA;   // h5 lives in hA
    int tid  = threadIdx.x;
    int base = blockIdx.x * 64;

    const float4* W4 = (const float4*)fW1;
    for (int i = tid; i < 64 * 16; i += 64) Ws[i] = W4[i];
    for (int i = tid; i < 64 * 64; i += 64) {
        int r = i >> 6, c = i & 63;
        int node = base + r;
        As[r * 65 + c] = (node < NN) ? A[node * HH + c] : 0.f;
    }
    __syncthreads();

    unsigned long long acc[32];
#pragma unroll
    for (int j = 0; j < 32; j++) acc[j] = 0ull;

#pragma unroll 4
    for (int k = 0; k < 64; k++) {
        float a = As[tid * 65 + k];
        unsigned long long aa;
        asm("mov.b64 %0, {%1, %1};" : "=l"(aa) : "f"(a));
        const ulonglong2* wrow = (const ulonglong2*)&Ws[k * 16];
#pragma unroll
        for (int j = 0; j < 16; j++) {
            ulonglong2 w2 = wrow[j];
            FMA2(acc[2 * j],     aa, w2.x);
            FMA2(acc[2 * j + 1], aa, w2.y);
        }
    }

    int node = base + tid;
    if (node < NN) {
        const float2* B2 = (const float2*)fb1;
        const float2* V2 = (const float2*)fW2;
        float r = fb2[0];
#pragma unroll
        for (int j = 0; j < 32; j++) {
            float lo, hi;
            asm("mov.b64 {%0, %1}, %2;" : "=f"(lo), "=f"(hi) : "l"(acc[j]));
            float2 b = B2[j], v = V2[j];
            float zx = fmaxf(lo + b.x, 0.f);
            float zy = fmaxf(hi + b.y, 0.f);
            r = fmaf(zx, v.x, r);
            r = fmaf(zy, v.y, r);
        }
        out[node] = r;
    }
}

// ---------------- launch ----------------
extern "C" void kernel_launch(void* const* d_in, const int* in_sizes, int n_in,
                              void* d_out, int out_size) {
    const float* x   = (const float*)d_in[0];
    const int*   ei  = (const int*)d_in[1];    // int32 (JAX default x64-disabled)
    const float* ea  = (const float*)d_in[2];
    const float* W1  = (const float*)d_in[3];
    const float* b1  = (const float*)d_in[4];
    const float* W2  = (const float*)d_in[5];
    const float* b2  = (const float*)d_in[6];
    const float* W3  = (const float*)d_in[7];
    const float* b3  = (const float*)d_in[8];
    const float* W4  = (const float*)d_in[9];
    const float* b4  = (const float*)d_in[10];
    const float* W5  = (const float*)d_in[11];
    const float* b5  = (const float*)d_in[12];
    const float* fW1 = (const float*)d_in[13];
    const float* fb1 = (const float*)d_in[14];
    const float* fW2 = (const float*)d_in[15];
    const float* fb2 = (const float*)d_in[16];
    float* out = (float*)d_out;

    const int TB = 256;
    int nblkN  = (NN + TB - 1) / TB;
    int nblkE  = (EE + TB - 1) / TB;
    int nblkT  = (TOT + TB - 1) / TB;
    int nblkN1 = (NN + 1 + TB - 1) / TB;
    int scanB  = (NN + 1 + 1023) / 1024;          // 98
    int gemmB  = (NN + 63) / 64;                  // 1563
    int aggB   = (NN / 4 * 32) / TB;              // 3125 (4 nodes/warp)

    // graph prep (float atomics OK; 717 was the int64-index bug)
    k_init  <<<nblkN, TB>>>();
    k_deg   <<<nblkE, TB>>>(ei, ea);
    k_scan1 <<<scanB, 1024>>>();
    k_scan3f<<<nblkN1, TB>>>(scanB);
    k_fill  <<<nblkT, TB>>>(ei, ea);

    // layer 1 (rank-1): h1 -> hA  (CSR already normalized)
    k_layer1<<<nblkN, TB>>>(x, W1, b1);

    // layer 2: g = half(hA @ W2) ; hB = relu(agg(g) + b2)
    k_gemm<<<gemmB, 64>>>(0, W2);
    k_agg <<<aggB, TB>>>(1, b2);
    // layer 3: hB -> hA
    k_gemm<<<gemmB, 64>>>(1, W3);
    k_agg <<<aggB, TB>>>(0, b3);
    // layer 4: hA -> hB
    k_gemm<<<gemmB, 64>>>(0, W4);
    k_agg <<<aggB, TB>>>(1, b4);
    // layer 5: hB -> hA
    k_gemm<<<gemmB, 64>>>(1, W5);
    k_agg <<<aggB, TB>>>(0, b5);

    // fused head
    k_final<<<gemmB, 64>>>(fW1, fb1, fW2, fb2, out);
}